// round 3
// baseline (speedup 1.0000x reference)
#include <cuda_runtime.h>
#include <cuda_fp16.h>
#include <cstdint>

// ---------------- constants ----------------
constexpr int TILE        = 64;     // edges per tile
constexpr int THREADS     = 384;    // 8 MMA warps + 4 producer warps
constexpr int MMA_THREADS = 256;

constexpr int LDX  = 200;  // X stride (halfs): 400B -> +4 banks/row, conflict-free
constexpr int LDW  = 136;  // weight / O1 / Wrbf stride (halfs): 272B
constexpr int LDO  = 136;
constexpr int LDRB = 24;   // rbf16 stride (halfs): 48B

// byte offsets into dynamic smem (all 16B aligned)
constexpr int B_W1E = 0;                        // [192][136] half
constexpr int B_W2E = B_W1E + 192*LDW*2;        // [64][136]  (W2l | W2g)
constexpr int B_W1N = B_W2E + 64*LDW*2;
constexpr int B_W2N = B_W1N + 192*LDW*2;
constexpr int B_WRB = B_W2N + 64*LDW*2;         // [16][136]  (We^T | Wn^T, k-rows 9..15 = 0)
constexpr int B_X0  = B_WRB + 16*LDW*2;         // [64][200] half, double buffered
constexpr int B_X1  = B_X0  + 64*LDX*2;
constexpr int B_O1  = B_X1  + 64*LDX*2;         // [64][136] half (GEMM1 out, H|G)
constexpr int B_RB0 = B_O1  + 64*LDO*2;         // [64][24] half (rbf padded to 16), dbl
constexpr int B_RB1 = B_RB0 + 64*LDRB*2;
constexpr int B_B1E = B_RB1 + 64*LDRB*2;        // [128] float each
constexpr int B_B2E = B_B1E + 128*4;
constexpr int B_B1N = B_B2E + 128*4;
constexpr int B_B2N = B_B1N + 128*4;
constexpr int B_DS0 = B_B2N + 128*4;            // [64] int, dbl
constexpr int B_DS1 = B_DS0 + 64*4;
constexpr int SMEM_BYTES = B_DS1 + 64*4;        // = 220928 (~215.8 KB)

__device__ __forceinline__ float fsigmoid(float x) { return 1.0f / (1.0f + __expf(-x)); }

__device__ __forceinline__ uint32_t cvta_s(const void* p) {
    return (uint32_t)__cvta_generic_to_shared(p);
}

__device__ __forceinline__ void ldx4(uint32_t* r, uint32_t a) {
    asm volatile("ldmatrix.sync.aligned.m8n8.x4.shared.b16 {%0,%1,%2,%3}, [%4];\n"
                 : "=r"(r[0]), "=r"(r[1]), "=r"(r[2]), "=r"(r[3]) : "r"(a));
}
__device__ __forceinline__ void ldx4t(uint32_t* r, uint32_t a) {
    asm volatile("ldmatrix.sync.aligned.m8n8.x4.trans.shared.b16 {%0,%1,%2,%3}, [%4];\n"
                 : "=r"(r[0]), "=r"(r[1]), "=r"(r[2]), "=r"(r[3]) : "r"(a));
}
__device__ __forceinline__ void mma16816(float* c, const uint32_t* a, uint32_t b0, uint32_t b1) {
    asm volatile("mma.sync.aligned.m16n8k16.row.col.f32.f16.f16.f32 "
                 "{%0,%1,%2,%3}, {%4,%5,%6,%7}, {%8,%9}, {%0,%1,%2,%3};\n"
                 : "+f"(c[0]), "+f"(c[1]), "+f"(c[2]), "+f"(c[3])
                 : "r"(a[0]), "r"(a[1]), "r"(a[2]), "r"(a[3]), "r"(b0), "r"(b1));
}
__device__ __forceinline__ void bar_mma() {
    asm volatile("bar.sync 1, %0;\n" :: "n"(MMA_THREADS) : "memory");
}
__device__ __forceinline__ void st4h(__half* p, float4 v) {
    *(__half2*)(p)     = __floats2half2_rn(v.x, v.y);
    *(__half2*)(p + 2) = __floats2half2_rn(v.z, v.w);
}

// GEMM1: C[64x128] = X[64x192] @ W[192x128], bias+silu, store fp16 to O1.
// Warp tile m32 x n32: mi = w&1, ni = w>>1.
__device__ __forceinline__ void gemm1(const __half* X, const __half* W,
                                      const float* bias, __half* O, int lane, int w)
{
    const int mi = w & 1, ni = w >> 1;
    float acc[2][4][4];
    #pragma unroll
    for (int m = 0; m < 2; ++m)
        #pragma unroll
        for (int n = 0; n < 4; ++n)
            #pragma unroll
            for (int j = 0; j < 4; ++j) acc[m][n][j] = 0.0f;

    uint32_t aB = cvta_s(X + (mi*32 + (lane & 15)) * LDX + ((lane >> 4) << 3));
    uint32_t bB = cvta_s(W + (lane & 15) * LDW + ni*32 + ((lane >> 4) << 3));

    #pragma unroll
    for (int kt = 0; kt < 12; ++kt) {
        uint32_t a0[4], a1[4], b0[4], b1[4];
        ldx4 (a0, aB + kt*32);
        ldx4 (a1, aB + 16*LDX*2 + kt*32);
        ldx4t(b0, bB + kt*16*LDW*2);
        ldx4t(b1, bB + kt*16*LDW*2 + 32);
        mma16816(acc[0][0], a0, b0[0], b0[1]);
        mma16816(acc[0][1], a0, b0[2], b0[3]);
        mma16816(acc[0][2], a0, b1[0], b1[1]);
        mma16816(acc[0][3], a0, b1[2], b1[3]);
        mma16816(acc[1][0], a1, b0[0], b0[1]);
        mma16816(acc[1][1], a1, b0[2], b0[3]);
        mma16816(acc[1][2], a1, b1[0], b1[1]);
        mma16816(acc[1][3], a1, b1[2], b1[3]);
    }

    const int r0 = lane >> 2, cp = (lane & 3) << 1;
    #pragma unroll
    for (int m = 0; m < 2; ++m) {
        int row = mi*32 + m*16 + r0;
        #pragma unroll
        for (int nt = 0; nt < 4; ++nt) {
            int col = ni*32 + nt*8 + cp;
            float bb0 = bias[col], bb1 = bias[col + 1];
            float v0 = acc[m][nt][0] + bb0, v1 = acc[m][nt][1] + bb1;
            float v2 = acc[m][nt][2] + bb0, v3 = acc[m][nt][3] + bb1;
            v0 *= fsigmoid(v0); v1 *= fsigmoid(v1);
            v2 *= fsigmoid(v2); v3 *= fsigmoid(v3);
            *(__half2*)(O + row * LDO + col)       = __floats2half2_rn(v0, v1);
            *(__half2*)(O + (row + 8) * LDO + col) = __floats2half2_rn(v2, v3);
        }
    }
}

// GEMM2 (fused H & G branches) + rbf-GEMM + epilogue, all per-warp m16 x n32.
// mi = w>>1 (0..3), ni = w&1 (0..1). PATH: 0=edge, 1=node.
template <int PATH>
__device__ __forceinline__ void tail(
    const __half* O1, const __half* W2, const float* bias2,
    const __half* RB, const __half* WRB,
    __half* Xcur, const int* dstbuf,
    const float* __restrict__ edge_feat, float* __restrict__ out_e,
    float* __restrict__ out_v,
    long ebase, int E, int lane, int w)
{
    const int mi = w >> 1, ni = w & 1;
    float ah[4][4], ag[4][4], ar[4][4];
    #pragma unroll
    for (int n = 0; n < 4; ++n)
        #pragma unroll
        for (int j = 0; j < 4; ++j) { ah[n][j] = 0; ag[n][j] = 0; ar[n][j] = 0; }

    uint32_t aB = cvta_s(O1 + (mi*16 + (lane & 15)) * LDO + ((lane >> 4) << 3));
    uint32_t bB = cvta_s(W2 + (lane & 15) * LDW + ni*32 + ((lane >> 4) << 3));

    #pragma unroll
    for (int kt = 0; kt < 4; ++kt) {
        uint32_t af[4], agf[4], bh0[4], bh1[4], bg0[4], bg1[4];
        ldx4 (af,  aB + kt*32);
        ldx4 (agf, aB + 128 + kt*32);               // +64 halfs: gates half of O1
        uint32_t bk = bB + kt*16*LDW*2;
        ldx4t(bh0, bk);
        ldx4t(bh1, bk + 32);
        ldx4t(bg0, bk + 128);                       // +64 cols: W2g
        ldx4t(bg1, bk + 128 + 32);
        mma16816(ah[0], af, bh0[0], bh0[1]);
        mma16816(ah[1], af, bh0[2], bh0[3]);
        mma16816(ah[2], af, bh1[0], bh1[1]);
        mma16816(ah[3], af, bh1[2], bh1[3]);
        mma16816(ag[0], agf, bg0[0], bg0[1]);
        mma16816(ag[1], agf, bg0[2], bg0[3]);
        mma16816(ag[2], agf, bg1[0], bg1[1]);
        mma16816(ag[3], agf, bg1[2], bg1[3]);
    }

    // R = rbf @ W^T  (K=16, rbf cols 9..15 zero-padded — RB buffers are
    // zero-initialized once at kernel start; producers only write cols 0..8)
    {
        uint32_t aR = cvta_s(RB + (mi*16 + (lane & 15)) * LDRB + ((lane >> 4) << 3));
        uint32_t bR = cvta_s(WRB + (lane & 15) * LDW + PATH*64 + ni*32 + ((lane >> 4) << 3));
        uint32_t arf[4], br0[4], br1[4];
        ldx4 (arf, aR);
        ldx4t(br0, bR);
        ldx4t(br1, bR + 32);
        mma16816(ar[0], arf, br0[0], br0[1]);
        mma16816(ar[1], arf, br0[2], br0[3]);
        mma16816(ar[2], arf, br1[0], br1[1]);
        mma16816(ar[3], arf, br1[2], br1[3]);
    }

    const int r0 = lane >> 2, cp = (lane & 3) << 1;
    #pragma unroll
    for (int hf = 0; hf < 2; ++hf) {
        int row = mi*16 + r0 + hf*8;
        long e = ebase + row;
        if (e >= E) continue;
        int de = (PATH == 1) ? dstbuf[row] : 0;
        #pragma unroll
        for (int nt = 0; nt < 4; ++nt) {
            int col = ni*32 + nt*8 + cp;
            float h0 = ah[nt][hf*2 + 0] + bias2[col];
            float h1 = ah[nt][hf*2 + 1] + bias2[col + 1];
            float g0 = ag[nt][hf*2 + 0] + bias2[64 + col];
            float g1 = ag[nt][hf*2 + 1] + bias2[64 + col + 1];
            h0 *= fsigmoid(h0); h1 *= fsigmoid(h1);
            g0 = fsigmoid(g0);  g1 = fsigmoid(g1);
            float u0 = h0 * g0 * ar[nt][hf*2 + 0];
            float u1 = h1 * g1 * ar[nt][hf*2 + 1];
            if (PATH == 0) {
                float2 ef = *(const float2*)(edge_feat + e*64 + col);
                float o0 = ef.x + u0, o1 = ef.y + u1;
                *(float2*)(out_e + e*64 + col) = make_float2(o0, o1);
                *(__half2*)(Xcur + row * LDX + 128 + col) = __floats2half2_rn(o0, o1);
            } else {
                asm volatile("red.global.add.v2.f32 [%0], {%1,%2};\n"
                             :: "l"(out_v + (long)de*64 + col), "f"(u0), "f"(u1)
                             : "memory");
            }
        }
    }
}

// Producer: stage tile into buffer buf (X fp16, rbf fp16 cols 0..8, dst).
__device__ __forceinline__ void stage(
    __half* Xb, __half* RBb, int* DSTb,
    const float* __restrict__ node_feat, const float* __restrict__ edge_feat,
    const float* __restrict__ rbf, const int* __restrict__ src,
    const int* __restrict__ dst, long tile, int E, int ptid)
{
    const int row  = ptid & 63;
    const int part = ptid >> 6;
    const long e = tile * 64 + row;
    __half* xr = Xb + row * LDX;

    if (tile >= 0 && e < (long)E) {
        if (part == 0) {
            const int se = src[e];
            DSTb[row] = dst[e];
            const float4* vs = (const float4*)(node_feat + (long)se * 64);
            #pragma unroll
            for (int j = 0; j < 16; ++j) st4h(xr + j*4, vs[j]);
            const float4* ef = (const float4*)(edge_feat + e * 64);
            #pragma unroll
            for (int j = 0; j < 8; ++j) st4h(xr + 128 + j*4, ef[j]);
            __half* rb = RBb + row * LDRB;
            #pragma unroll
            for (int k = 0; k < 9; ++k) rb[k] = __float2half(rbf[e*9 + k]);
        } else {
            const int de = dst[e];
            const float4* vd = (const float4*)(node_feat + (long)de * 64);
            #pragma unroll
            for (int j = 0; j < 16; ++j) st4h(xr + 64 + j*4, vd[j]);
            const float4* ef = (const float4*)(edge_feat + e * 64);
            #pragma unroll
            for (int j = 8; j < 16; ++j) st4h(xr + 128 + j*4, ef[j]);
        }
    } else {
        const uint2 z = {0u, 0u};
        if (part == 0) {
            #pragma unroll
            for (int j = 0; j < 16; ++j) *(uint2*)(xr + j*4) = z;
            #pragma unroll
            for (int j = 0; j < 8; ++j)  *(uint2*)(xr + 128 + j*4) = z;
            __half* rb = RBb + row * LDRB;
            #pragma unroll
            for (int k = 0; k < 9; ++k) rb[k] = __half(0.0f);
            DSTb[row] = 0;
        } else {
            #pragma unroll
            for (int j = 0; j < 16; ++j) *(uint2*)(xr + 64 + j*4) = z;
            #pragma unroll
            for (int j = 8; j < 16; ++j) *(uint2*)(xr + 128 + j*4) = z;
        }
    }
}

__global__ void __launch_bounds__(THREADS, 1) m3gnet_fused(
    const float* __restrict__ node_feat, const float* __restrict__ edge_feat,
    const float* __restrict__ rbf, const int* __restrict__ src, const int* __restrict__ dst,
    const float* __restrict__ el1w, const float* __restrict__ el1b,
    const float* __restrict__ el2w, const float* __restrict__ el2b,
    const float* __restrict__ eg1w, const float* __restrict__ eg1b,
    const float* __restrict__ eg2w, const float* __restrict__ eg2b,
    const float* __restrict__ nl1w, const float* __restrict__ nl1b,
    const float* __restrict__ nl2w, const float* __restrict__ nl2b,
    const float* __restrict__ ng1w, const float* __restrict__ ng1b,
    const float* __restrict__ ng2w, const float* __restrict__ ng2b,
    const float* __restrict__ eww, const float* __restrict__ nww,
    float* __restrict__ out_e, float* __restrict__ out_v,
    int E, int ntiles)
{
    extern __shared__ char smem[];
    __half* s_w1e = (__half*)(smem + B_W1E);
    __half* s_w2e = (__half*)(smem + B_W2E);
    __half* s_w1n = (__half*)(smem + B_W1N);
    __half* s_w2n = (__half*)(smem + B_W2N);
    __half* s_wrb = (__half*)(smem + B_WRB);
    __half* s_x[2]  = { (__half*)(smem + B_X0),  (__half*)(smem + B_X1)  };
    __half* s_o1  = (__half*)(smem + B_O1);
    __half* s_rb[2] = { (__half*)(smem + B_RB0), (__half*)(smem + B_RB1) };
    float*  s_b1e = (float*)(smem + B_B1E);
    float*  s_b2e = (float*)(smem + B_B2E);
    float*  s_b1n = (float*)(smem + B_B1N);
    float*  s_b2n = (float*)(smem + B_B2N);
    int*    s_ds[2] = { (int*)(smem + B_DS0), (int*)(smem + B_DS1) };

    const int tid = threadIdx.x;

    // ---- one-time zero of rbf buffers: cols 9..23 must be 0 for the K=16 MMA ----
    for (int i = tid; i < 2 * 64 * LDRB; i += THREADS)
        ((__half*)(smem + B_RB0))[i] = __half(0.0f);

    // ---- one-time weight staging ----
    for (int i = tid; i < 64 * 192; i += THREADS) {
        int n = i / 192, k = i - n * 192;
        s_w1e[k * LDW + n]      = __float2half(el1w[i]);
        s_w1e[k * LDW + 64 + n] = __float2half(eg1w[i]);
        s_w1n[k * LDW + n]      = __float2half(nl1w[i]);
        s_w1n[k * LDW + 64 + n] = __float2half(ng1w[i]);
    }
    for (int i = tid; i < 64 * 64; i += THREADS) {
        int n = i / 64, k = i - n * 64;
        s_w2e[k * LDW + n]      = __float2half(el2w[i]);
        s_w2e[k * LDW + 64 + n] = __float2half(eg2w[i]);
        s_w2n[k * LDW + n]      = __float2half(nl2w[i]);
        s_w2n[k * LDW + 64 + n] = __float2half(ng2w[i]);
    }
    // Wrbf: [16][We^T | Wn^T], rows k=9..15 zero
    for (int i = tid; i < 128 * 16; i += THREADS) {
        int c = i >> 4, k = i & 15;
        float v = 0.0f;
        if (k < 9) v = (c < 64) ? eww[c * 9 + k] : nww[(c - 64) * 9 + k];
        s_wrb[k * LDW + c] = __float2half(v);
    }
    if (tid < 64) {
        s_b1e[tid] = el1b[tid]; s_b1e[64 + tid] = eg1b[tid];
        s_b2e[tid] = el2b[tid]; s_b2e[64 + tid] = eg2b[tid];
        s_b1n[tid] = nl1b[tid]; s_b1n[64 + tid] = ng1b[tid];
        s_b2n[tid] = nl2b[tid]; s_b2n[64 + tid] = ng2b[tid];
    }
    __syncthreads();

    const int lane = tid & 31;
    const int warp = tid >> 5;

    // prologue: stage first tile into buffer 0
    if (warp >= 8) {
        stage(s_x[0], s_rb[0], s_ds[0], node_feat, edge_feat, rbf, src, dst,
              (long)blockIdx.x, E, tid - MMA_THREADS);
    }
    __syncthreads();

    int it = 0;
    for (long t = blockIdx.x; t < ntiles; t += gridDim.x, ++it) {
        const int cur = it & 1;
        const long ebase = t * TILE;

        if (warp < 8) {
            // ---- EDGE path ----
            gemm1(s_x[cur], s_w1e, s_b1e, s_o1, lane, warp);
            bar_mma();
            tail<0>(s_o1, s_w2e, s_b2e, s_rb[cur], s_wrb, s_x[cur], s_ds[cur],
                    edge_feat, out_e, out_v, ebase, E, lane, warp);
            bar_mma();   // e_new patched into X before node GEMM1
            // ---- NODE path ----
            gemm1(s_x[cur], s_w1n, s_b1n, s_o1, lane, warp);
            bar_mma();
            tail<1>(s_o1, s_w2n, s_b2n, s_rb[cur], s_wrb, s_x[cur], s_ds[cur],
                    edge_feat, out_e, out_v, ebase, E, lane, warp);
        } else {
            const long tn = t + gridDim.x;
            stage(s_x[cur ^ 1], s_rb[cur ^ 1], s_ds[cur ^ 1],
                  node_feat, edge_feat, rbf, src, dst,
                  (tn < ntiles) ? tn : (long)-1, E, tid - MMA_THREADS);
        }
        __syncthreads();
    }
}

__global__ void copy_v_init(const float* __restrict__ nf, float* __restrict__ outv, int n4)
{
    for (int i = blockIdx.x * blockDim.x + threadIdx.x; i < n4; i += gridDim.x * blockDim.x)
        ((float4*)outv)[i] = ((const float4*)nf)[i];
}

extern "C" void kernel_launch(void* const* d_in, const int* in_sizes, int n_in,
                              void* d_out, int out_size)
{
    const float* node_feat = (const float*)d_in[0];
    const float* edge_feat = (const float*)d_in[1];
    const float* rbf       = (const float*)d_in[2];
    const int*   src       = (const int*)d_in[3];
    const int*   dst       = (const int*)d_in[4];
    const float* el1w = (const float*)d_in[5];  const float* el1b = (const float*)d_in[6];
    const float* el2w = (const float*)d_in[7];  const float* el2b = (const float*)d_in[8];
    const float* eg1w = (const float*)d_in[9];  const float* eg1b = (const float*)d_in[10];
    const float* eg2w = (const float*)d_in[11]; const float* eg2b = (const float*)d_in[12];
    const float* nl1w = (const float*)d_in[13]; const float* nl1b = (const float*)d_in[14];
    const float* nl2w = (const float*)d_in[15]; const float* nl2b = (const float*)d_in[16];
    const float* ng1w = (const float*)d_in[17]; const float* ng1b = (const float*)d_in[18];
    const float* ng2w = (const float*)d_in[19]; const float* ng2b = (const float*)d_in[20];
    const float* eww  = (const float*)d_in[21]; const float* nww  = (const float*)d_in[22];

    const int E = in_sizes[3];
    const int N = in_sizes[0] / 64;
    float* out_e = (float*)d_out;
    float* out_v = out_e + (size_t)E * 64;

    int sms = 148;
    cudaDeviceGetAttribute(&sms, cudaDevAttrMultiProcessorCount, 0);

    cudaFuncSetAttribute(m3gnet_fused, cudaFuncAttributeMaxDynamicSharedMemorySize, SMEM_BYTES);

    copy_v_init<<<sms * 4, 256>>>(node_feat, out_v, N * 16);

    const int ntiles = (E + TILE - 1) / TILE;
    m3gnet_fused<<<sms, THREADS, SMEM_BYTES>>>(
        node_feat, edge_feat, rbf, src, dst,
        el1w, el1b, el2w, el2b, eg1w, eg1b, eg2w, eg2b,
        nl1w, nl1b, nl2w, nl2b, ng1w, ng1b, ng2w, ng2b,
        eww, nww, out_e, out_v, E, ntiles);
}

// round 4
// speedup vs baseline: 3.9838x; 3.9838x over previous
#include <cuda_runtime.h>
#include <cuda_fp16.h>
#include <cstdint>

// ---------------- constants ----------------
constexpr int THREADS = 256;     // 8 autonomous warps, each owns 16 edges/tile
constexpr int NWARP   = 8;

constexpr int LDX  = 200;  // X stride (halfs): 400B
constexpr int LDW  = 136;  // weight stride (halfs): 272B
constexpr int LDRB = 24;   // rbf16 stride (halfs)

// byte offsets into dynamic smem
constexpr int B_W1E = 0;                        // [192][136] half  (l1|g1)
constexpr int B_W2E = B_W1E + 192*LDW*2;        // [64][136]        (l2|g2)
constexpr int B_W1N = B_W2E + 64*LDW*2;
constexpr int B_W2N = B_W1N + 192*LDW*2;
constexpr int B_WRB = B_W2N + 64*LDW*2;         // [16][136] (We^T | Wn^T, k=9..15 zero)
constexpr int B_B1E = B_WRB + 16*LDW*2;         // [128] float each
constexpr int B_B2E = B_B1E + 128*4;
constexpr int B_B1N = B_B2E + 128*4;
constexpr int B_B2N = B_B1N + 128*4;
constexpr int B_X   = B_B2N + 128*4;            // 8 x [16][200] half (per warp)
constexpr int B_RB  = B_X   + NWARP*16*LDX*2;   // 8 x [16][24] half
constexpr int SMEM_BYTES = B_RB + NWARP*16*LDRB*2;   // = 203008

__device__ __forceinline__ float fsig(float x) {
    float t;
    asm("tanh.approx.f32 %0, %1;\n" : "=f"(t) : "f"(x * 0.5f));
    return fmaf(t, 0.5f, 0.5f);
}
__device__ __forceinline__ float fsilu(float x) { return x * fsig(x); }

__device__ __forceinline__ uint32_t cvta_s(const void* p) {
    return (uint32_t)__cvta_generic_to_shared(p);
}
__device__ __forceinline__ void ldx4(uint32_t* r, uint32_t a) {
    asm volatile("ldmatrix.sync.aligned.m8n8.x4.shared.b16 {%0,%1,%2,%3}, [%4];\n"
                 : "=r"(r[0]), "=r"(r[1]), "=r"(r[2]), "=r"(r[3]) : "r"(a));
}
__device__ __forceinline__ void ldx4t(uint32_t* r, uint32_t a) {
    asm volatile("ldmatrix.sync.aligned.m8n8.x4.trans.shared.b16 {%0,%1,%2,%3}, [%4];\n"
                 : "=r"(r[0]), "=r"(r[1]), "=r"(r[2]), "=r"(r[3]) : "r"(a));
}
__device__ __forceinline__ void mma16816(float* c, const uint32_t* a, uint32_t b0, uint32_t b1) {
    asm volatile("mma.sync.aligned.m16n8k16.row.col.f32.f16.f16.f32 "
                 "{%0,%1,%2,%3}, {%4,%5,%6,%7}, {%8,%9}, {%0,%1,%2,%3};\n"
                 : "+f"(c[0]), "+f"(c[1]), "+f"(c[2]), "+f"(c[3])
                 : "r"(a[0]), "r"(a[1]), "r"(a[2]), "r"(a[3]), "r"(b0), "r"(b1));
}
__device__ __forceinline__ uint32_t h2pack(float a, float b) {
    __half2 h = __floats2half2_rn(a, b);
    return *(uint32_t*)&h;
}
__device__ __forceinline__ void st4h(__half* p, float4 v) {
    uint2 u;
    u.x = h2pack(v.x, v.y);
    u.y = h2pack(v.z, v.w);
    *(uint2*)p = u;
}

// GEMM1: per-warp m16 x n128 x k192; bias + silu; results converted to fp16
// A-fragments for GEMM2: ah (cols 0-63), ag (cols 64-127), each [4 kb][4 regs].
__device__ __forceinline__ void gemm1_reg(const __half* X, const __half* W,
                                          const float* bias,
                                          uint32_t* ah, uint32_t* ag, int lane)
{
    float acc[16][4];
    #pragma unroll
    for (int n = 0; n < 16; ++n)
        #pragma unroll
        for (int j = 0; j < 4; ++j) acc[n][j] = 0.0f;

    uint32_t aB = cvta_s(X + (lane & 15) * LDX + ((lane >> 4) << 3));
    uint32_t bB = cvta_s(W + (lane & 15) * LDW + ((lane >> 4) << 3));

    #pragma unroll
    for (int kt = 0; kt < 12; ++kt) {
        uint32_t a[4];
        ldx4(a, aB + kt * 32);
        uint32_t bk = bB + kt * 16 * LDW * 2;
        #pragma unroll
        for (int nb2 = 0; nb2 < 8; ++nb2) {
            uint32_t b[4];
            ldx4t(b, bk + nb2 * 32);
            mma16816(acc[2*nb2],     a, b[0], b[1]);
            mma16816(acc[2*nb2 + 1], a, b[2], b[3]);
        }
    }

    const int cp = (lane & 3) << 1;
    #pragma unroll
    for (int nb = 0; nb < 16; ++nb) {
        int c = nb * 8 + cp;
        float v0 = fsilu(acc[nb][0] + bias[c]);
        float v1 = fsilu(acc[nb][1] + bias[c + 1]);
        float v2 = fsilu(acc[nb][2] + bias[c]);
        float v3 = fsilu(acc[nb][3] + bias[c + 1]);
        uint32_t* dstv = (nb < 8) ? ah : ag;
        int kb = (nb & 7) >> 1, odd = nb & 1;
        dstv[kb*4 + odd*2 + 0] = h2pack(v0, v1);
        dstv[kb*4 + odd*2 + 1] = h2pack(v2, v3);
    }
}

// GEMM2 (H and G branches, A in registers) + rbf mini-GEMM + gate combine.
// Output u[8][4]: gated, rbf-scaled update values in C-fragment layout.
__device__ __forceinline__ void tail_reg(const uint32_t* ah, const uint32_t* ag,
                                         const __half* W2, const float* b2,
                                         const __half* RB, const __half* WRB,
                                         int path, float u[8][4], int lane)
{
    float acch[8][4], accg[8][4];
    #pragma unroll
    for (int n = 0; n < 8; ++n)
        #pragma unroll
        for (int j = 0; j < 4; ++j) { acch[n][j] = 0; accg[n][j] = 0; }

    uint32_t bB = cvta_s(W2 + (lane & 15) * LDW + ((lane >> 4) << 3));
    #pragma unroll
    for (int kt = 0; kt < 4; ++kt) {
        uint32_t bk = bB + kt * 16 * LDW * 2;
        #pragma unroll
        for (int nb2 = 0; nb2 < 4; ++nb2) {
            uint32_t b[4];
            ldx4t(b, bk + nb2 * 32);
            mma16816(acch[2*nb2],     ah + kt*4, b[0], b[1]);
            mma16816(acch[2*nb2 + 1], ah + kt*4, b[2], b[3]);
        }
        #pragma unroll
        for (int nb2 = 0; nb2 < 4; ++nb2) {
            uint32_t b[4];
            ldx4t(b, bk + 128 + nb2 * 32);
            mma16816(accg[2*nb2],     ag + kt*4, b[0], b[1]);
            mma16816(accg[2*nb2 + 1], ag + kt*4, b[2], b[3]);
        }
    }

    // R = rbf @ W^T (K=16, zero-padded)
    float accr[8][4];
    #pragma unroll
    for (int n = 0; n < 8; ++n)
        #pragma unroll
        for (int j = 0; j < 4; ++j) accr[n][j] = 0;
    {
        uint32_t ar[4];
        ldx4(ar, cvta_s(RB + (lane & 15) * LDRB + ((lane >> 4) << 3)));
        uint32_t bR = cvta_s(WRB + (lane & 15) * LDW + ((lane >> 4) << 3)) + path * 128;
        #pragma unroll
        for (int nb2 = 0; nb2 < 4; ++nb2) {
            uint32_t b[4];
            ldx4t(b, bR + nb2 * 32);
            mma16816(accr[2*nb2],     ar, b[0], b[1]);
            mma16816(accr[2*nb2 + 1], ar, b[2], b[3]);
        }
    }

    const int cp = (lane & 3) << 1;
    #pragma unroll
    for (int ob = 0; ob < 8; ++ob) {
        int c = ob * 8 + cp;
        float bh0 = b2[c], bh1 = b2[c + 1];
        float bg0 = b2[64 + c], bg1 = b2[64 + c + 1];
        u[ob][0] = fsilu(acch[ob][0] + bh0) * fsig(accg[ob][0] + bg0) * accr[ob][0];
        u[ob][1] = fsilu(acch[ob][1] + bh1) * fsig(accg[ob][1] + bg1) * accr[ob][1];
        u[ob][2] = fsilu(acch[ob][2] + bh0) * fsig(accg[ob][2] + bg0) * accr[ob][2];
        u[ob][3] = fsilu(acch[ob][3] + bh1) * fsig(accg[ob][3] + bg1) * accr[ob][3];
    }
}

__global__ void __launch_bounds__(THREADS, 1) m3gnet_fused(
    const float* __restrict__ node_feat, const float* __restrict__ edge_feat,
    const float* __restrict__ rbf, const int* __restrict__ src, const int* __restrict__ dst,
    const float* __restrict__ el1w, const float* __restrict__ el1b,
    const float* __restrict__ el2w, const float* __restrict__ el2b,
    const float* __restrict__ eg1w, const float* __restrict__ eg1b,
    const float* __restrict__ eg2w, const float* __restrict__ eg2b,
    const float* __restrict__ nl1w, const float* __restrict__ nl1b,
    const float* __restrict__ nl2w, const float* __restrict__ nl2b,
    const float* __restrict__ ng1w, const float* __restrict__ ng1b,
    const float* __restrict__ ng2w, const float* __restrict__ ng2b,
    const float* __restrict__ eww, const float* __restrict__ nww,
    float* __restrict__ out_e, float* __restrict__ out_v,
    int E)
{
    extern __shared__ char smem[];
    __half* s_w1e = (__half*)(smem + B_W1E);
    __half* s_w2e = (__half*)(smem + B_W2E);
    __half* s_w1n = (__half*)(smem + B_W1N);
    __half* s_w2n = (__half*)(smem + B_W2N);
    __half* s_wrb = (__half*)(smem + B_WRB);
    float*  s_b1e = (float*)(smem + B_B1E);
    float*  s_b2e = (float*)(smem + B_B2E);
    float*  s_b1n = (float*)(smem + B_B1N);
    float*  s_b2n = (float*)(smem + B_B2N);
    __half* s_x   = (__half*)(smem + B_X);
    __half* s_rb  = (__half*)(smem + B_RB);

    const int tid = threadIdx.x;

    // one-time zero of rbf tiles (cols 9..23 must stay 0 for the K=16 MMA)
    for (int i = tid; i < NWARP * 16 * LDRB; i += THREADS)
        s_rb[i] = __half(0.0f);

    // one-time weight staging
    for (int i = tid; i < 64 * 192; i += THREADS) {
        int n = i / 192, k = i - n * 192;
        s_w1e[k * LDW + n]      = __float2half(el1w[i]);
        s_w1e[k * LDW + 64 + n] = __float2half(eg1w[i]);
        s_w1n[k * LDW + n]      = __float2half(nl1w[i]);
        s_w1n[k * LDW + 64 + n] = __float2half(ng1w[i]);
    }
    for (int i = tid; i < 64 * 64; i += THREADS) {
        int n = i / 64, k = i - n * 64;
        s_w2e[k * LDW + n]      = __float2half(el2w[i]);
        s_w2e[k * LDW + 64 + n] = __float2half(eg2w[i]);
        s_w2n[k * LDW + n]      = __float2half(nl2w[i]);
        s_w2n[k * LDW + 64 + n] = __float2half(ng2w[i]);
    }
    for (int i = tid; i < 128 * 16; i += THREADS) {
        int c = i >> 4, k = i & 15;
        float v = 0.0f;
        if (k < 9) v = (c < 64) ? eww[c * 9 + k] : nww[(c - 64) * 9 + k];
        s_wrb[k * LDW + c] = __float2half(v);
    }
    if (tid < 64) {
        s_b1e[tid] = el1b[tid]; s_b1e[64 + tid] = eg1b[tid];
        s_b2e[tid] = el2b[tid]; s_b2e[64 + tid] = eg2b[tid];
        s_b1n[tid] = nl1b[tid]; s_b1n[64 + tid] = ng1b[tid];
        s_b2n[tid] = nl2b[tid]; s_b2n[64 + tid] = ng2b[tid];
    }
    __syncthreads();
    // ---- from here on: NO block barriers; each warp is autonomous ----

    const int lane = tid & 31;
    const int warp = tid >> 5;
    __half* xb = s_x  + warp * 16 * LDX;
    __half* rb = s_rb + warp * 16 * LDRB;
    const int r0 = lane >> 2, cp = (lane & 3) << 1;
    const int srow = lane & 15, sec = lane >> 4;

    const long nwt = ((long)E + 15) >> 4;
    for (long wt = (long)blockIdx.x * NWARP + warp; wt < nwt; wt += (long)gridDim.x * NWARP) {
        const long ebase = wt << 4;

        // ---- stage own 16 edges: X = [vi | vj | ef] fp16, rbf fp16 ----
        {
            const long e = ebase + srow;
            const bool v = e < (long)E;
            __half* xr = xb + srow * LDX;
            if (sec == 0) {
                if (v) {
                    const int se = src[e];
                    const float4* vs = (const float4*)(node_feat + (long)se * 64);
                    #pragma unroll
                    for (int j = 0; j < 16; ++j) st4h(xr + j * 4, vs[j]);
                    const float4* ef = (const float4*)(edge_feat + e * 64);
                    #pragma unroll
                    for (int j = 0; j < 8; ++j) st4h(xr + 128 + j * 4, ef[j]);
                    #pragma unroll
                    for (int k = 0; k < 9; ++k)
                        rb[srow * LDRB + k] = __float2half(rbf[e * 9 + k]);
                } else {
                    const uint2 z = {0u, 0u};
                    #pragma unroll
                    for (int j = 0; j < 16; ++j) *(uint2*)(xr + j * 4) = z;
                    #pragma unroll
                    for (int j = 0; j < 8; ++j) *(uint2*)(xr + 128 + j * 4) = z;
                    #pragma unroll
                    for (int k = 0; k < 9; ++k) rb[srow * LDRB + k] = __half(0.0f);
                }
            } else {
                if (v) {
                    const int de = dst[e];
                    const float4* vd = (const float4*)(node_feat + (long)de * 64);
                    #pragma unroll
                    for (int j = 0; j < 16; ++j) st4h(xr + 64 + j * 4, vd[j]);
                    const float4* ef = (const float4*)(edge_feat + e * 64);
                    #pragma unroll
                    for (int j = 8; j < 16; ++j) st4h(xr + 128 + j * 4, ef[j]);
                } else {
                    const uint2 z = {0u, 0u};
                    #pragma unroll
                    for (int j = 0; j < 16; ++j) *(uint2*)(xr + 64 + j * 4) = z;
                    #pragma unroll
                    for (int j = 8; j < 16; ++j) *(uint2*)(xr + 128 + j * 4) = z;
                }
            }
        }

        // prefetch fp32 residuals + dst indices for this thread's output rows
        const long e0 = ebase + r0, e1 = e0 + 8;
        const bool v0 = e0 < (long)E, v1 = e1 < (long)E;
        float2 ef0[8], ef1[8];
        int de0 = 0, de1 = 0;
        if (v0) {
            de0 = dst[e0];
            #pragma unroll
            for (int ob = 0; ob < 8; ++ob)
                ef0[ob] = *(const float2*)(edge_feat + e0 * 64 + ob * 8 + cp);
        }
        if (v1) {
            de1 = dst[e1];
            #pragma unroll
            for (int ob = 0; ob < 8; ++ob)
                ef1[ob] = *(const float2*)(edge_feat + e1 * 64 + ob * 8 + cp);
        }
        __syncwarp();

        uint32_t ah[16], ag[16];
        float u[8][4];

        // ================= EDGE PATH =================
        gemm1_reg(xb, s_w1e, s_b1e, ah, ag, lane);
        tail_reg(ah, ag, s_w2e, s_b2e, rb, s_wrb, 0, u, lane);
        #pragma unroll
        for (int ob = 0; ob < 8; ++ob) {
            int c = ob * 8 + cp;
            if (v0) {
                float o0 = ef0[ob].x + u[ob][0], o1 = ef0[ob].y + u[ob][1];
                *(float2*)(out_e + e0 * 64 + c) = make_float2(o0, o1);
                *(uint32_t*)(xb + r0 * LDX + 128 + c) = h2pack(o0, o1);
            }
            if (v1) {
                float o2 = ef1[ob].x + u[ob][2], o3 = ef1[ob].y + u[ob][3];
                *(float2*)(out_e + e1 * 64 + c) = make_float2(o2, o3);
                *(uint32_t*)(xb + (r0 + 8) * LDX + 128 + c) = h2pack(o2, o3);
            }
        }
        __syncwarp();   // e_new patch visible to warp before node GEMM1

        // ================= NODE PATH =================
        gemm1_reg(xb, s_w1n, s_b1n, ah, ag, lane);
        tail_reg(ah, ag, s_w2n, s_b2n, rb, s_wrb, 1, u, lane);
        #pragma unroll
        for (int ob = 0; ob < 8; ++ob) {
            int c = ob * 8 + cp;
            if (v0)
                asm volatile("red.global.add.v2.f32 [%0], {%1,%2};\n"
                             :: "l"(out_v + (long)de0 * 64 + c), "f"(u[ob][0]), "f"(u[ob][1])
                             : "memory");
            if (v1)
                asm volatile("red.global.add.v2.f32 [%0], {%1,%2};\n"
                             :: "l"(out_v + (long)de1 * 64 + c), "f"(u[ob][2]), "f"(u[ob][3])
                             : "memory");
        }
        __syncwarp();
    }
}

__global__ void copy_v_init(const float* __restrict__ nf, float* __restrict__ outv, int n4)
{
    for (int i = blockIdx.x * blockDim.x + threadIdx.x; i < n4; i += gridDim.x * blockDim.x)
        ((float4*)outv)[i] = ((const float4*)nf)[i];
}

extern "C" void kernel_launch(void* const* d_in, const int* in_sizes, int n_in,
                              void* d_out, int out_size)
{
    const float* node_feat = (const float*)d_in[0];
    const float* edge_feat = (const float*)d_in[1];
    const float* rbf       = (const float*)d_in[2];
    const int*   src       = (const int*)d_in[3];
    const int*   dst       = (const int*)d_in[4];
    const float* el1w = (const float*)d_in[5];  const float* el1b = (const float*)d_in[6];
    const float* el2w = (const float*)d_in[7];  const float* el2b = (const float*)d_in[8];
    const float* eg1w = (const float*)d_in[9];  const float* eg1b = (const float*)d_in[10];
    const float* eg2w = (const float*)d_in[11]; const float* eg2b = (const float*)d_in[12];
    const float* nl1w = (const float*)d_in[13]; const float* nl1b = (const float*)d_in[14];
    const float* nl2w = (const float*)d_in[15]; const float* nl2b = (const float*)d_in[16];
    const float* ng1w = (const float*)d_in[17]; const float* ng1b = (const float*)d_in[18];
    const float* ng2w = (const float*)d_in[19]; const float* ng2b = (const float*)d_in[20];
    const float* eww  = (const float*)d_in[21]; const float* nww  = (const float*)d_in[22];

    const int E = in_sizes[3];
    const int N = in_sizes[0] / 64;
    float* out_e = (float*)d_out;
    float* out_v = out_e + (size_t)E * 64;

    int sms = 148;
    cudaDeviceGetAttribute(&sms, cudaDevAttrMultiProcessorCount, 0);

    cudaFuncSetAttribute(m3gnet_fused, cudaFuncAttributeMaxDynamicSharedMemorySize, SMEM_BYTES);

    copy_v_init<<<sms * 4, 256>>>(node_feat, out_v, N * 16);

    m3gnet_fused<<<sms, THREADS, SMEM_BYTES>>>(
        node_feat, edge_feat, rbf, src, dst,
        el1w, el1b, el2w, el2b, eg1w, eg1b, eg2w, eg2b,
        nl1w, nl1b, nl2w, nl2b, ng1w, ng1b, ng2w, ng2b,
        eww, nww, out_e, out_v, E);
}